// round 4
// baseline (speedup 1.0000x reference)
#include <cuda_runtime.h>
#include <cuda_bf16.h>
#include <cstdint>

#define BS_    2
#define SEQ    1024
#define DMODEL 1024
#define NH     16
#define HD     64
#define MM     32
#define ROWS   (BS_*SEQ)

// ---------------- scratch (device globals) ----------------
__device__ float g_qkv[ROWS*3*DMODEL];
__device__ float g_mem[ROWS*DMODEL];
__device__ float g_hid[ROWS*DMODEL];
__device__ __nv_bfloat16 g_h1h[ROWS*DMODEL],  g_h1l[ROWS*DMODEL];
__device__ __nv_bfloat16 g_atth[ROWS*DMODEL], g_attl[ROWS*DMODEL];
__device__ __nv_bfloat16 g_h2h[ROWS*DMODEL],  g_h2l[ROWS*DMODEL];
__device__ __nv_bfloat16 g_ffh[ROWS*4*DMODEL], g_ffl[ROWS*4*DMODEL];
__device__ __nv_bfloat16 g_wqh[DMODEL*3*DMODEL], g_wql[DMODEL*3*DMODEL];
__device__ __nv_bfloat16 g_wph[DMODEL*DMODEL],   g_wpl[DMODEL*DMODEL];
__device__ __nv_bfloat16 g_wfh[DMODEL*4*DMODEL], g_wfl[DMODEL*4*DMODEL];
__device__ __nv_bfloat16 g_woh[4*DMODEL*DMODEL], g_wol[4*DMODEL*DMODEL];

// ---------------- helpers ----------------
__device__ __forceinline__ uint32_t smem_to_u32(const void* p) {
    uint32_t a;
    asm("{ .reg .u64 t; cvta.to.shared.u64 t, %1; cvt.u32.u64 %0, t; }" : "=r"(a) : "l"(p));
    return a;
}
__device__ __forceinline__ void cp16(uint32_t s, const void* g) {
    asm volatile("cp.async.cg.shared.global [%0], [%1], 16;" :: "r"(s), "l"(g));
}
#define CP_COMMIT() asm volatile("cp.async.commit_group;" ::: "memory")
#define CP_WAIT1()  asm volatile("cp.async.wait_group 1;" ::: "memory")

__device__ __forceinline__ void ldsm4(uint32_t* r, uint32_t addr) {
    asm volatile("ldmatrix.sync.aligned.m8n8.x4.shared.b16 {%0,%1,%2,%3}, [%4];"
        : "=r"(r[0]), "=r"(r[1]), "=r"(r[2]), "=r"(r[3]) : "r"(addr));
}
__device__ __forceinline__ void mma16816(float* d, const uint32_t* a, const uint32_t* b) {
    asm volatile(
      "mma.sync.aligned.m16n8k16.row.col.f32.bf16.bf16.f32 "
      "{%0,%1,%2,%3}, {%4,%5,%6,%7}, {%8,%9}, {%0,%1,%2,%3};"
      : "+f"(d[0]), "+f"(d[1]), "+f"(d[2]), "+f"(d[3])
      : "r"(a[0]), "r"(a[1]), "r"(a[2]), "r"(a[3]), "r"(b[0]), "r"(b[1]));
}

__device__ __forceinline__ float gelu_new(float x) {
    float x3 = x * x * x;
    float t  = tanhf(0.7978845608028654f * (x + 0.044715f * x3));
    return 0.5f * x * (1.f + t);
}
__device__ __forceinline__ uint32_t pack_bf2(float x, float y) {
    __nv_bfloat162 t = __floats2bfloat162_rn(x, y);
    return *reinterpret_cast<uint32_t*>(&t);
}
__device__ __forceinline__ float bf_hi(float x) {
    return __bfloat162float(__float2bfloat16(x));
}

// ---------------- weight convert: W[K,N] f32 -> Whi/Wlo [N,K] bf16 --------
__global__ void __launch_bounds__(256) wconv_kernel(
    const float* __restrict__ W, __nv_bfloat16* __restrict__ hi,
    __nv_bfloat16* __restrict__ lo, int K, int N)
{
    __shared__ float s[32][33];
    const int tx = threadIdx.x & 31, ty = threadIdx.x >> 5;
    const int n0 = blockIdx.x * 32, k0 = blockIdx.y * 32;
    #pragma unroll
    for (int i = 0; i < 4; i++)
        s[ty + 8*i][tx] = W[(size_t)(k0 + ty + 8*i) * N + n0 + tx];
    __syncthreads();
    #pragma unroll
    for (int i = 0; i < 4; i++) {
        int n = ty + 8*i;
        float v = s[tx][n];
        float h = bf_hi(v);
        size_t o = (size_t)(n0 + n) * K + k0 + tx;
        hi[o] = __float2bfloat16(v);
        lo[o] = __float2bfloat16(v - h);
    }
}

// ---------------- LayerNorm -> hi/lo bf16 ----------------
__global__ void __launch_bounds__(256) ln_kernel(
    const float* __restrict__ x, const float* __restrict__ g,
    const float* __restrict__ b, __nv_bfloat16* __restrict__ yh,
    __nv_bfloat16* __restrict__ yl)
{
    const int row = blockIdx.x, tid = threadIdx.x;
    const float* xr = x + (size_t)row * DMODEL;
    float4 v = *(const float4*)(xr + tid * 4);
    float s  = v.x + v.y + v.z + v.w;
    float s2 = v.x*v.x + v.y*v.y + v.z*v.z + v.w*v.w;
    __shared__ float rs[8], rs2[8];
    #pragma unroll
    for (int o = 16; o; o >>= 1) {
        s  += __shfl_xor_sync(0xffffffffu, s,  o);
        s2 += __shfl_xor_sync(0xffffffffu, s2, o);
    }
    const int w = tid >> 5, l = tid & 31;
    if (!l) { rs[w] = s; rs2[w] = s2; }
    __syncthreads();
    s = 0.f; s2 = 0.f;
    #pragma unroll
    for (int i = 0; i < 8; i++) { s += rs[i]; s2 += rs2[i]; }
    const float mean = s * (1.f / DMODEL);
    const float var  = s2 * (1.f / DMODEL) - mean * mean;
    const float rstd = rsqrtf(var + 1e-5f);
    const int c = tid * 4;
    float4 gg = *(const float4*)(g + c);
    float4 bb = *(const float4*)(b + c);
    float4 o;
    o.x = (v.x - mean) * rstd * gg.x + bb.x;
    o.y = (v.y - mean) * rstd * gg.y + bb.y;
    o.z = (v.z - mean) * rstd * gg.z + bb.z;
    o.w = (v.w - mean) * rstd * gg.w + bb.w;
    uint2 hh, ll;
    hh.x = pack_bf2(o.x, o.y); hh.y = pack_bf2(o.z, o.w);
    ll.x = pack_bf2(o.x - bf_hi(o.x), o.y - bf_hi(o.y));
    ll.y = pack_bf2(o.z - bf_hi(o.z), o.w - bf_hi(o.w));
    const size_t idx = (size_t)row * DMODEL + c;
    *(uint2*)(yh + idx) = hh;
    *(uint2*)(yl + idx) = ll;
}

// ---------------- mma.sync bf16x3 GEMM (ldmatrix mainloop) ------------------
// C[M,N] = A[M,K] @ B^T (B stored [N,K]); A,B as hi/lo bf16 pairs.
// CTA 128x128, 8 warps (2x4) of 64x32. K-chunk 32, cp.async x2 buffers.
// SMEM row stride 40 bf16 (80B): 16B-aligned rows, conflict-free ldmatrix.
// EPI 0: +bias->f32 | 1: gated+residual->f32 | 2: gelu->bf16 hi/lo | 3: +bias+aux1->f32
#define PADK    40
#define STAGE_B (128*PADK*2)            // 10240 B per array
#define GSTAGE  (4*STAGE_B)             // 40960 B per stage
#define GEMM_SMEM (2*GSTAGE)            // 81920 B

template<int EPI>
__global__ void __launch_bounds__(256) gemm_mma_kernel(
    const __nv_bfloat16* __restrict__ Ah, const __nv_bfloat16* __restrict__ Al,
    const __nv_bfloat16* __restrict__ Bh, const __nv_bfloat16* __restrict__ Bl,
    const float* __restrict__ bias,
    float* __restrict__ Cf, __nv_bfloat16* __restrict__ Ch, __nv_bfloat16* __restrict__ Cl,
    int M, int N, int K,
    const float* __restrict__ aux1, const float* __restrict__ aux2,
    const float* __restrict__ gp)
{
    extern __shared__ char smp[];
    const uint32_t sb = smem_to_u32(smp);
    const int tid = threadIdx.x;
    const int wid = tid >> 5, lane = tid & 31;
    const int wm = wid & 1, wn = wid >> 1;           // warp tile: 64x32
    const int bm = blockIdx.y, bn = blockIdx.x;
    const int NC = K >> 5;

    const size_t Abase = (size_t)bm * 128 * K;
    const size_t Bbase = (size_t)bn * 128 * K;

    float acc[4][4][4];
    #pragma unroll
    for (int i = 0; i < 4; i++)
        #pragma unroll
        for (int j = 0; j < 4; j++)
            #pragma unroll
            for (int x = 0; x < 4; x++) acc[i][j][x] = 0.f;

    // cp.async producer mapping: per array, 2 rows/thread, 16B quarter each
    const int crow = tid >> 2;          // 0..63
    const int cq   = tid & 3;           // 16B quarter within 64B row

    auto issue = [&](int buf, int kt) {
        const int k0 = kt << 5;
        const uint32_t sbase = sb + buf * GSTAGE;
        #pragma unroll
        for (int h = 0; h < 2; h++) {
            const int row = crow + h * 64;
            const uint32_t so = (uint32_t)(row * (PADK*2) + cq * 16);
            const size_t go = (size_t)row * K + k0 + cq * 8;
            cp16(sbase + so,               Ah + Abase + go);
            cp16(sbase + STAGE_B + so,     Al + Abase + go);
            cp16(sbase + 2*STAGE_B + so,   Bh + Bbase + go);
            cp16(sbase + 3*STAGE_B + so,   Bl + Bbase + go);
        }
    };

    issue(0, 0); CP_COMMIT();
    if (NC > 1) issue(1, 1);
    CP_COMMIT();

    // ldmatrix per-lane address components
    // A tile (16x32 per mt, per h/l, per ks): rows wm*64 + mt*16 + (lane&15),
    //   kbyte = (lane>>4)*16 + ks*32
    // B tile (8x32 per nt, per h/l): rows wn*32 + nt*8 + (lane&7),
    //   kbyte = (lane>>3)*16   (x4 covers b0/b1 for both ks)
    const uint32_t aRow = (uint32_t)(wm * 64 + (lane & 15));
    const uint32_t aKb  = (uint32_t)((lane >> 4) * 16);
    const uint32_t bRow = (uint32_t)(wn * 32 + (lane & 7));
    const uint32_t bKb  = (uint32_t)((lane >> 3) * 16);
    const uint32_t aOff = aRow * (PADK*2) + aKb;
    const uint32_t bOff = bRow * (PADK*2) + bKb;

    for (int c = 0; c < NC; c++) {
        CP_WAIT1();
        __syncthreads();
        const uint32_t s0 = sb + (c & 1) * GSTAGE;

        // B fragments: one ldmatrix.x4 per (nt, h/l) covers both k16 steps
        uint32_t bh[2][4][2], bl[2][4][2];
        #pragma unroll
        for (int nt = 0; nt < 4; nt++) {
            uint32_t r[4];
            const uint32_t ba = s0 + bOff + (uint32_t)(nt * 8 * (PADK*2));
            ldsm4(r, ba + 2*STAGE_B);
            bh[0][nt][0] = r[0]; bh[0][nt][1] = r[1];
            bh[1][nt][0] = r[2]; bh[1][nt][1] = r[3];
            ldsm4(r, ba + 3*STAGE_B);
            bl[0][nt][0] = r[0]; bl[0][nt][1] = r[1];
            bl[1][nt][0] = r[2]; bl[1][nt][1] = r[3];
        }
        #pragma unroll
        for (int ks = 0; ks < 2; ks++) {
            uint32_t ah[4][4], al[4][4];
            #pragma unroll
            for (int mt = 0; mt < 4; mt++) {
                const uint32_t aa = s0 + aOff + (uint32_t)(mt * 16 * (PADK*2) + ks * 32);
                ldsm4(ah[mt], aa);
                ldsm4(al[mt], aa + STAGE_B);
            }
            #pragma unroll
            for (int mt = 0; mt < 4; mt++)
                #pragma unroll
                for (int nt = 0; nt < 4; nt++) {
                    mma16816(acc[mt][nt], ah[mt], bh[ks][nt]);
                    mma16816(acc[mt][nt], ah[mt], bl[ks][nt]);
                    mma16816(acc[mt][nt], al[mt], bh[ks][nt]);
                }
        }
        __syncthreads();
        if (c + 2 < NC) issue(c & 1, c + 2);
        CP_COMMIT();
    }

    // ---------------- epilogue ----------------
    const int r = lane >> 2, q = lane & 3;
    const float g = (EPI == 1) ? *gp : 0.f;
    #pragma unroll
    for (int mt = 0; mt < 4; mt++) {
        #pragma unroll
        for (int nt = 0; nt < 4; nt++) {
            const int col = bn * 128 + wn * 32 + nt * 8 + q * 2;
            const float2 bb = *(const float2*)(bias + col);
            #pragma unroll
            for (int hh = 0; hh < 2; hh++) {
                const int row = bm * 128 + wm * 64 + mt * 16 + r + hh * 8;
                const size_t o = (size_t)row * N + col;
                float v0 = acc[mt][nt][hh*2+0] + bb.x;
                float v1 = acc[mt][nt][hh*2+1] + bb.y;
                if (EPI == 1) {
                    float2 a1 = *(const float2*)(aux1 + o);
                    float2 a2 = *(const float2*)(aux2 + o);
                    v0 = (1.f - g) * v0 + g * a1.x + a2.x;
                    v1 = (1.f - g) * v1 + g * a1.y + a2.y;
                }
                if (EPI == 3) {
                    float2 a1 = *(const float2*)(aux1 + o);
                    v0 += a1.x; v1 += a1.y;
                }
                if (EPI == 2) {
                    v0 = gelu_new(v0); v1 = gelu_new(v1);
                    *(uint32_t*)(Ch + o) = pack_bf2(v0, v1);
                    *(uint32_t*)(Cl + o) = pack_bf2(v0 - bf_hi(v0), v1 - bf_hi(v1));
                } else {
                    *(float2*)(Cf + o) = make_float2(v0, v1);
                }
            }
        }
    }
}

// ---------------- KNN memory attention ----------------
__global__ void __launch_bounds__(256) memattn_kernel(
    const float* __restrict__ qkv, const float* __restrict__ mkv,
    float* __restrict__ outm)
{
    const int row = blockIdx.x, tid = threadIdx.x;
    __shared__ float sc[NH * MM];
    float4 qv = *(const float4*)(qkv + (size_t)row * 3072 + tid * 4);
    qv.x *= 0.125f; qv.y *= 0.125f; qv.z *= 0.125f; qv.w *= 0.125f;
    const float* kbase = mkv + (size_t)row * MM * 2 * DMODEL;
    const int h = tid >> 4;
    #pragma unroll 4
    for (int m = 0; m < MM; m++) {
        float4 kk = *(const float4*)(kbase + (size_t)m * 2 * DMODEL + tid * 4);
        float d = qv.x * kk.x + qv.y * kk.y + qv.z * kk.z + qv.w * kk.w;
        #pragma unroll
        for (int o = 8; o; o >>= 1) d += __shfl_xor_sync(0xffffffffu, d, o);
        if ((tid & 15) == 0) sc[h * MM + m] = d;
    }
    __syncthreads();
    if (tid < NH) {
        float mx = -1e30f;
        #pragma unroll
        for (int m = 0; m < MM; m++) mx = fmaxf(mx, sc[tid * MM + m]);
        float s = 0.f;
        #pragma unroll
        for (int m = 0; m < MM; m++) {
            float e = __expf(sc[tid * MM + m] - mx);
            sc[tid * MM + m] = e; s += e;
        }
        float inv = 1.f / s;
        #pragma unroll
        for (int m = 0; m < MM; m++) sc[tid * MM + m] *= inv;
    }
    __syncthreads();
    float4 acc = make_float4(0.f, 0.f, 0.f, 0.f);
    #pragma unroll 4
    for (int m = 0; m < MM; m++) {
        float w = sc[h * MM + m];
        float4 vv = *(const float4*)(kbase + (size_t)m * 2 * DMODEL + DMODEL + tid * 4);
        acc.x += w * vv.x; acc.y += w * vv.y; acc.z += w * vv.z; acc.w += w * vv.w;
    }
    *(float4*)(outm + (size_t)row * DMODEL + tid * 4) = acc;
}

// ---------------- causal flash attention, fp32, writes hi/lo bf16 ----------
#define QST 65
#define FLASH_SMEM ((2 * 64 * QST + 64 * 64) * 4)
__global__ void __launch_bounds__(256) flash_kernel(
    const float* __restrict__ qkv, __nv_bfloat16* __restrict__ outh,
    __nv_bfloat16* __restrict__ outl)
{
    extern __shared__ float sm[];
    float* Qs = sm;
    float* KP = sm + 64 * QST;
    float* Vs = sm + 2 * 64 * QST;
    const int tid = threadIdx.x;
    const int ty = tid >> 4, tx = tid & 15;
    const int qt = blockIdx.x;
    const int b = blockIdx.y >> 4, h = blockIdx.y & 15;
    const int qbase = qt * 64;
    const size_t srow = (size_t)b * SEQ;
    const int li = tid >> 2;
    const int lc0 = (tid & 3) * 4;

    {
        const float* gq = qkv + (srow + qbase + li) * (size_t)3072 + h * 64;
        #pragma unroll
        for (int u = 0; u < 4; u++) {
            const int c = lc0 + u * 16;
            float4 v = *(const float4*)(gq + c);
            Qs[li*QST+c]   = v.x * 0.125f; Qs[li*QST+c+1] = v.y * 0.125f;
            Qs[li*QST+c+2] = v.z * 0.125f; Qs[li*QST+c+3] = v.w * 0.125f;
        }
    }
    float m_i[4], l_i[4], o[4][4];
    #pragma unroll
    for (int v = 0; v < 4; v++) {
        m_i[v] = -1e30f; l_i[v] = 0.f;
        o[v][0] = o[v][1] = o[v][2] = o[v][3] = 0.f;
    }

    for (int kt = 0; kt <= qt; kt++) {
        __syncthreads();
        const int kbase = kt * 64;
        const float* gk = qkv + (srow + kbase + li) * (size_t)3072 + 1024 + h * 64;
        const float* gv = qkv + (srow + kbase + li) * (size_t)3072 + 2048 + h * 64;
        #pragma unroll
        for (int u = 0; u < 4; u++) {
            const int c = lc0 + u * 16;
            float4 kv = *(const float4*)(gk + c);
            KP[li*QST+c]   = kv.x; KP[li*QST+c+1] = kv.y;
            KP[li*QST+c+2] = kv.z; KP[li*QST+c+3] = kv.w;
            float4 vv = *(const float4*)(gv + c);
            *(float4*)&Vs[li * 64 + c] = vv;
        }
        __syncthreads();
        float s[4][4];
        #pragma unroll
        for (int v = 0; v < 4; v++) s[v][0] = s[v][1] = s[v][2] = s[v][3] = 0.f;
        #pragma unroll 8
        for (int dd = 0; dd < 64; dd++) {
            float a[4], bf[4];
            #pragma unroll
            for (int v = 0; v < 4; v++) a[v]  = Qs[(ty * 4 + v) * QST + dd];
            #pragma unroll
            for (int u = 0; u < 4; u++) bf[u] = KP[(tx * 4 + u) * QST + dd];
            #pragma unroll
            for (int v = 0; v < 4; v++)
                #pragma unroll
                for (int u = 0; u < 4; u++) s[v][u] += a[v] * bf[u];
        }
        if (kt == qt) {
            #pragma unroll
            for (int v = 0; v < 4; v++)
                #pragma unroll
                for (int u = 0; u < 4; u++)
                    if (tx * 4 + u > ty * 4 + v) s[v][u] = -1e30f;
        }
        float mnew[4], alpha[4], p[4][4], rsum[4];
        #pragma unroll
        for (int v = 0; v < 4; v++) {
            float mx = fmaxf(fmaxf(s[v][0], s[v][1]), fmaxf(s[v][2], s[v][3]));
            #pragma unroll
            for (int off = 8; off; off >>= 1)
                mx = fmaxf(mx, __shfl_xor_sync(0xffffffffu, mx, off));
            mnew[v]  = fmaxf(m_i[v], mx);
            alpha[v] = __expf(m_i[v] - mnew[v]);
            float rs = 0.f;
            #pragma unroll
            for (int u = 0; u < 4; u++) { p[v][u] = __expf(s[v][u] - mnew[v]); rs += p[v][u]; }
            #pragma unroll
            for (int off = 8; off; off >>= 1)
                rs += __shfl_xor_sync(0xffffffffu, rs, off);
            rsum[v] = rs;
        }
        #pragma unroll
        for (int v = 0; v < 4; v++) {
            l_i[v] = alpha[v] * l_i[v] + rsum[v];
            m_i[v] = mnew[v];
            o[v][0] *= alpha[v]; o[v][1] *= alpha[v]; o[v][2] *= alpha[v]; o[v][3] *= alpha[v];
        }
        __syncthreads();
        #pragma unroll
        for (int v = 0; v < 4; v++)
            #pragma unroll
            for (int u = 0; u < 4; u++)
                KP[(ty * 4 + v) * QST + tx * 4 + u] = p[v][u];
        __syncthreads();
        #pragma unroll 4
        for (int jj = 0; jj < 64; jj++) {
            float4 bv = *(const float4*)&Vs[jj * 64 + tx * 4];
            #pragma unroll
            for (int v = 0; v < 4; v++) {
                float a = KP[(ty * 4 + v) * QST + jj];
                o[v][0] += a * bv.x; o[v][1] += a * bv.y;
                o[v][2] += a * bv.z; o[v][3] += a * bv.w;
            }
        }
    }
    #pragma unroll
    for (int v = 0; v < 4; v++) {
        const float inv = 1.f / l_i[v];
        const int qi = qbase + ty * 4 + v;
        float4 ov = make_float4(o[v][0]*inv, o[v][1]*inv, o[v][2]*inv, o[v][3]*inv);
        uint2 hh, ll;
        hh.x = pack_bf2(ov.x, ov.y); hh.y = pack_bf2(ov.z, ov.w);
        ll.x = pack_bf2(ov.x - bf_hi(ov.x), ov.y - bf_hi(ov.y));
        ll.y = pack_bf2(ov.z - bf_hi(ov.z), ov.w - bf_hi(ov.w));
        const size_t oo = (srow + qi) * (size_t)DMODEL + h * 64 + tx * 4;
        *(uint2*)(outh + oo) = hh;
        *(uint2*)(outl + oo) = ll;
    }
}

// ------------------------------ launcher ------------------------------------
extern "C" void kernel_launch(void* const* d_in, const int* in_sizes, int n_in,
                              void* d_out, int out_size)
{
    (void)in_sizes; (void)n_in; (void)out_size;
    const float* prev  = (const float*)d_in[0];
    const float* memkv = (const float*)d_in[1];
    const float* gval  = (const float*)d_in[2];
    const float* ln1g  = (const float*)d_in[3];
    const float* ln1b  = (const float*)d_in[4];
    const float* attnw = (const float*)d_in[5];
    const float* attnb = (const float*)d_in[6];
    const float* cprw  = (const float*)d_in[7];
    const float* cprb  = (const float*)d_in[8];
    const float* ln2g  = (const float*)d_in[9];
    const float* ln2b  = (const float*)d_in[10];
    const float* fcw   = (const float*)d_in[11];
    const float* fcb   = (const float*)d_in[12];
    const float* pw    = (const float*)d_in[13];
    const float* pb    = (const float*)d_in[14];
    float* out = (float*)d_out;

    float *qkv, *mem, *hid;
    __nv_bfloat16 *h1h, *h1l, *atth, *attl, *h2h, *h2l, *ffh, *ffl;
    __nv_bfloat16 *wqh, *wql, *wph, *wpl, *wfh, *wfl, *woh, *wol;
    cudaGetSymbolAddress((void**)&qkv, g_qkv);
    cudaGetSymbolAddress((void**)&mem, g_mem);
    cudaGetSymbolAddress((void**)&hid, g_hid);
    cudaGetSymbolAddress((void**)&h1h, g_h1h);  cudaGetSymbolAddress((void**)&h1l, g_h1l);
    cudaGetSymbolAddress((void**)&atth, g_atth); cudaGetSymbolAddress((void**)&attl, g_attl);
    cudaGetSymbolAddress((void**)&h2h, g_h2h);  cudaGetSymbolAddress((void**)&h2l, g_h2l);
    cudaGetSymbolAddress((void**)&ffh, g_ffh);  cudaGetSymbolAddress((void**)&ffl, g_ffl);
    cudaGetSymbolAddress((void**)&wqh, g_wqh);  cudaGetSymbolAddress((void**)&wql, g_wql);
    cudaGetSymbolAddress((void**)&wph, g_wph);  cudaGetSymbolAddress((void**)&wpl, g_wpl);
    cudaGetSymbolAddress((void**)&wfh, g_wfh);  cudaGetSymbolAddress((void**)&wfl, g_wfl);
    cudaGetSymbolAddress((void**)&woh, g_woh);  cudaGetSymbolAddress((void**)&wol, g_wol);

    cudaFuncSetAttribute(flash_kernel, cudaFuncAttributeMaxDynamicSharedMemorySize, FLASH_SMEM);
    cudaFuncSetAttribute(gemm_mma_kernel<0>, cudaFuncAttributeMaxDynamicSharedMemorySize, GEMM_SMEM);
    cudaFuncSetAttribute(gemm_mma_kernel<1>, cudaFuncAttributeMaxDynamicSharedMemorySize, GEMM_SMEM);
    cudaFuncSetAttribute(gemm_mma_kernel<2>, cudaFuncAttributeMaxDynamicSharedMemorySize, GEMM_SMEM);
    cudaFuncSetAttribute(gemm_mma_kernel<3>, cudaFuncAttributeMaxDynamicSharedMemorySize, GEMM_SMEM);

    // 0) weight converts (transpose + bf16 split)
    wconv_kernel<<<dim3(3*DMODEL/32, DMODEL/32), 256>>>(attnw, wqh, wql, DMODEL, 3*DMODEL);
    wconv_kernel<<<dim3(DMODEL/32,   DMODEL/32), 256>>>(cprw, wph, wpl, DMODEL, DMODEL);
    wconv_kernel<<<dim3(4*DMODEL/32, DMODEL/32), 256>>>(fcw, wfh, wfl, DMODEL, 4*DMODEL);
    wconv_kernel<<<dim3(DMODEL/32, 4*DMODEL/32), 256>>>(pw, woh, wol, 4*DMODEL, DMODEL);
    // 1) LN1 -> h1 hi/lo
    ln_kernel<<<ROWS, 256>>>(prev, ln1g, ln1b, h1h, h1l);
    // 2) qkv = h1 @ c_attn + b (f32)
    gemm_mma_kernel<0><<<dim3(24, 16), 256, GEMM_SMEM>>>(h1h, h1l, wqh, wql, attnb,
        qkv, nullptr, nullptr, ROWS, 3*DMODEL, DMODEL, nullptr, nullptr, nullptr);
    // 3) memory attention
    memattn_kernel<<<ROWS, 256>>>(qkv, memkv, mem);
    // 4) causal self-attention -> att hi/lo
    flash_kernel<<<dim3(SEQ/64, BS_*NH), 256, FLASH_SMEM>>>(qkv, atth, attl);
    // 5) hid = (1-g)*(att@c_proj+b) + g*mem + prev
    gemm_mma_kernel<1><<<dim3(8, 16), 256, GEMM_SMEM>>>(atth, attl, wph, wpl, cprb,
        hid, nullptr, nullptr, ROWS, DMODEL, DMODEL, mem, prev, gval);
    // 6) LN2 -> h2 hi/lo
    ln_kernel<<<ROWS, 256>>>(hid, ln2g, ln2b, h2h, h2l);
    // 7) ff = gelu(h2 @ fc + b) -> hi/lo
    gemm_mma_kernel<2><<<dim3(32, 16), 256, GEMM_SMEM>>>(h2h, h2l, wfh, wfl, fcb,
        nullptr, ffh, ffl, ROWS, 4*DMODEL, DMODEL, nullptr, nullptr, nullptr);
    // 8) out = ff @ proj + b + hid
    gemm_mma_kernel<3><<<dim3(8, 16), 256, GEMM_SMEM>>>(ffh, ffl, woh, wol, pb,
        out, nullptr, nullptr, ROWS, DMODEL, 4*DMODEL, hid, nullptr, nullptr);
}